// round 5
// baseline (speedup 1.0000x reference)
#include <cuda_runtime.h>
#include <cstdint>

#define NF 40
#define NP 780        // 40*39/2
#define ED 64
#define AS 32
#define THREADS 256
#define CP 128        // pairs per chunk
#define NCH 7         // ceil(780/128)
#define NPAD (NCH*CP) // 896

// ---- dynamic smem byte offsets (all 16B-aligned) ----
#define IP_OFF    0        // [64 d][128 pairs] f32            32768
#define XS_OFF    32768    // [40][65] f32 (pitch 65, scalar)  10432
#define WSP_OFF   43200    // [64 d][32 cols] u64 splatted     16384
#define OFFS_OFF  59584    // [896] u32 packed byte-offsets     3584
#define LOG_OFF   63168    // [896] f32                         3584
#define PART_OFF  66752    // [128][9] f32                      4608
#define AB_OFF    71360    // 32 f32
#define PW_OFF    71488    // 32 f32
#define FW_OFF    71616    // 64 f32
#define RMAX_OFF  71872    // 8 f32
#define RSUM_OFF  71904    // 8 f32
#define RED_OFF   71936    // 64 f32
#define SMEM_TOTAL 72192

__device__ __forceinline__ unsigned long long splat2(float a) {
    unsigned long long r;
    asm("mov.b64 %0, {%1, %1};" : "=l"(r) : "f"(a));
    return r;
}
__device__ __forceinline__ void unpack2(unsigned long long v, float& a, float& b) {
    asm("mov.b64 {%0, %1}, %2;" : "=f"(a), "=f"(b) : "l"(v));
}
#define FMA2(acc, a, b) asm("fma.rn.f32x2 %0, %1, %2, %0;" : "+l"(acc) : "l"(a), "l"(b))

__global__ __launch_bounds__(THREADS) void afm_kernel(
    const float* __restrict__ x,
    const float* __restrict__ attn_w,
    const float* __restrict__ attn_b,
    const float* __restrict__ proj_w,
    const float* __restrict__ proj_b,
    const float* __restrict__ fc_w,
    const float* __restrict__ fc_b,
    float* __restrict__ out)
{
    extern __shared__ char smem[];
    float* xs        = (float*)(smem + XS_OFF);
    float* logits_s  = (float*)(smem + LOG_OFF);
    float* part      = (float*)(smem + PART_OFF);
    float* ab_s      = (float*)(smem + AB_OFF);
    float* pw_s      = (float*)(smem + PW_OFF);
    float* fw_s      = (float*)(smem + FW_OFF);
    float* rmax      = (float*)(smem + RMAX_OFF);
    float* rsum      = (float*)(smem + RSUM_OFF);
    float* red_s     = (float*)(smem + RED_OFF);
    uint32_t* offs   = (uint32_t*)(smem + OFFS_OFF);

    const int tid  = threadIdx.x;
    const int lane = tid & 31;
    const int wid  = tid >> 5;
    const int b    = blockIdx.x;

    // ---- Phase 1: stage inputs ----
    const float* xb = x + (long long)b * (NF * ED);
    for (int idx = tid; idx < NF * ED; idx += THREADS)
        xs[(idx >> 6) * 65 + (idx & 63)] = xb[idx];

    // W pre-splatted u64: Wsp[d*32 + c] = {w, w}
    unsigned long long* Wsp = (unsigned long long*)(smem + WSP_OFF);
    for (int e = tid; e < ED * AS; e += THREADS)
        Wsp[e] = splat2(attn_w[e]);

    if (tid < AS) { pw_s[tid] = proj_w[tid]; ab_s[tid] = attn_b[tid]; }
    if (tid < ED) fw_s[tid] = fc_w[tid];

    // packed xs byte-offsets per pair: low16 = i*260, high16 = j*260
    for (int p = tid; p < NPAD; p += THREADS) {
        uint32_t o = 0;
        if (p < NP) {
            int i = 0, rem = p;
            while (rem >= NF - 1 - i) { rem -= NF - 1 - i; ++i; }
            int j = i + 1 + rem;
            o = (uint32_t)(i * 260) | ((uint32_t)(j * 260) << 16);
        }
        offs[p] = o;
    }
    const float pb = proj_b[0];
    __syncthreads();

    // ---- Phase 2: chunked tiled GEMM ----
    const int psub = lane >> 3;                    // 0..3 : pair subgroup
    const int cgrp = lane & 7;                     // 0..7 : col group (4 cols)
    const int ppB  = (wid * 16 + psub * 4) * 4;    // byte offset of 4 pairs in IP row
    const int wB   = cgrp * 32;                    // byte offset of 4 splatted cols
    const int pg   = lane;                         // build: pair-group (4 pairs)
    const uint4* offs4 = (const uint4*)(smem + OFFS_OFF);
    const char* xsc = (const char*)xs;

    const float pwc0 = pw_s[cgrp * 4 + 0], pwc1 = pw_s[cgrp * 4 + 1];
    const float pwc2 = pw_s[cgrp * 4 + 2], pwc3 = pw_s[cgrp * 4 + 3];

    for (int t = 0; t < NCH; ++t) {
        const int cbase = t * CP;

        // ---- build IP tile [d][128 pairs]: thread = 4 pairs x 8 d's ----
        {
            const uint4 oo = offs4[t * 32 + pg];   // 4 pairs' packed offsets
#pragma unroll
            for (int it = 0; it < 8; ++it) {
                const int d = wid + it * 8;
                const char* xsd = xsc + d * 4;
                float4 pr;
                pr.x = *(const float*)(xsd + (oo.x & 0xffffu)) * *(const float*)(xsd + (oo.x >> 16));
                pr.y = *(const float*)(xsd + (oo.y & 0xffffu)) * *(const float*)(xsd + (oo.y >> 16));
                pr.z = *(const float*)(xsd + (oo.z & 0xffffu)) * *(const float*)(xsd + (oo.z >> 16));
                pr.w = *(const float*)(xsd + (oo.w & 0xffffu)) * *(const float*)(xsd + (oo.w >> 16));
                *(float4*)(smem + IP_OFF + d * 512 + pg * 16) = pr;
            }
        }
        __syncthreads();

        // ---- GEMM: 4 pairs (packed 2+2) x 4 cols per thread, K=64 ----
        unsigned long long acc0[4], acc1[4];
#pragma unroll
        for (int c = 0; c < 4; ++c) {
            unsigned long long bs = splat2(ab_s[cgrp * 4 + c]);
            acc0[c] = bs;
            acc1[c] = bs;
        }
#pragma unroll 16
        for (int d = 0; d < ED; ++d) {
            ulonglong2 ip = *(const ulonglong2*)(smem + IP_OFF + d * 512 + ppB);
            ulonglong2 wa = *(const ulonglong2*)(smem + WSP_OFF + d * 256 + wB);
            ulonglong2 wb = *(const ulonglong2*)(smem + WSP_OFF + d * 256 + wB + 16);
            FMA2(acc0[0], ip.x, wa.x); FMA2(acc1[0], ip.y, wa.x);
            FMA2(acc0[1], ip.x, wa.y); FMA2(acc1[1], ip.y, wa.y);
            FMA2(acc0[2], ip.x, wb.x); FMA2(acc1[2], ip.y, wb.x);
            FMA2(acc0[3], ip.x, wb.y); FMA2(acc1[3], ip.y, wb.y);
        }

        // ---- epilogue: relu + proj partial, 4 pairs per thread ----
        {
            float lg0 = 0.f, lg1 = 0.f, lg2 = 0.f, lg3 = 0.f;
            float a, c2;
#pragma unroll
            for (int c = 0; c < 4; ++c) {
                const float pw = (c == 0) ? pwc0 : (c == 1) ? pwc1 : (c == 2) ? pwc2 : pwc3;
                unpack2(acc0[c], a, c2);
                lg0 += fmaxf(a, 0.f) * pw;
                lg1 += fmaxf(c2, 0.f) * pw;
                unpack2(acc1[c], a, c2);
                lg2 += fmaxf(a, 0.f) * pw;
                lg3 += fmaxf(c2, 0.f) * pw;
            }
            const int pc = wid * 16 + psub * 4;
            part[(pc + 0) * 9 + cgrp] = lg0;
            part[(pc + 1) * 9 + cgrp] = lg1;
            part[(pc + 2) * 9 + cgrp] = lg2;
            part[(pc + 3) * 9 + cgrp] = lg3;
        }
        __syncthreads();

        // ---- reduce 8 col-group partials -> logit ----
        if (tid < CP) {
            const int p = cbase + tid;
            if (p < NP) {
                float s = pb;
#pragma unroll
                for (int k = 0; k < 8; ++k) s += part[tid * 9 + k];
                logits_s[p] = s;
            }
        }
        // next build writes IP only; the sync after build protects part
    }
    __syncthreads();

    // ---- Phase 3: softmax over 780 (unnormalized; fold 1/S at end) ----
    float lm = -3.4e38f;
    for (int p = tid; p < NP; p += THREADS) lm = fmaxf(lm, logits_s[p]);
#pragma unroll
    for (int o = 16; o > 0; o >>= 1) lm = fmaxf(lm, __shfl_xor_sync(0xffffffffu, lm, o));
    if (lane == 0) rmax[wid] = lm;
    __syncthreads();

    float gmax = rmax[0];
#pragma unroll
    for (int wq = 1; wq < 8; ++wq) gmax = fmaxf(gmax, rmax[wq]);

    float ls = 0.f;
    for (int p = tid; p < NP; p += THREADS) {
        float e = __expf(logits_s[p] - gmax);
        logits_s[p] = e;
        ls += e;
    }
#pragma unroll
    for (int o = 16; o > 0; o >>= 1) ls += __shfl_xor_sync(0xffffffffu, ls, o);
    if (lane == 0) rsum[wid] = ls;
    __syncthreads();

    // ---- Phase 4: weighted sum over pairs (recompute ip), fc dot ----
    float* part4 = (float*)(smem + IP_OFF);   // IP tile is dead; 8 warps x 64 dims
    float accL = 0.f, accH = 0.f;
    for (int p = wid; p < NP; p += 8) {
        const float s = logits_s[p];
        const uint32_t o = offs[p];
        const char* xi = xsc + (o & 0xffffu);
        const char* xj = xsc + (o >> 16);
        accL += s * (*(const float*)(xi + lane * 4)       * *(const float*)(xj + lane * 4));
        accH += s * (*(const float*)(xi + 128 + lane * 4) * *(const float*)(xj + 128 + lane * 4));
    }
    part4[wid * 64 + lane]      = accL;
    part4[wid * 64 + 32 + lane] = accH;
    __syncthreads();

    if (tid < 64) {
        float v = 0.f;
#pragma unroll
        for (int wq = 0; wq < 8; ++wq) v += part4[wq * 64 + tid];
        red_s[tid] = v * fw_s[tid];
    }
    __syncthreads();

    if (tid == 0) {
        float S = 0.f;
#pragma unroll
        for (int wq = 0; wq < 8; ++wq) S += rsum[wq];
        float tt = 0.f;
#pragma unroll
        for (int k = 0; k < 64; ++k) tt += red_s[k];
        out[b] = tt / S + fc_b[0];
    }
}

extern "C" void kernel_launch(void* const* d_in, const int* in_sizes, int n_in,
                              void* d_out, int out_size)
{
    const float* x      = (const float*)d_in[0];
    const float* attn_w = (const float*)d_in[1];
    const float* attn_b = (const float*)d_in[2];
    const float* proj_w = (const float*)d_in[3];
    const float* proj_b = (const float*)d_in[4];
    const float* fc_w   = (const float*)d_in[5];
    const float* fc_b   = (const float*)d_in[6];
    float* out = (float*)d_out;

    cudaFuncSetAttribute(afm_kernel, cudaFuncAttributeMaxDynamicSharedMemorySize, SMEM_TOTAL);
    afm_kernel<<<2048, THREADS, SMEM_TOTAL>>>(x, attn_w, attn_b, proj_w, proj_b, fc_w, fc_b, out);
}

// round 6
// speedup vs baseline: 2.5310x; 2.5310x over previous
#include <cuda_runtime.h>
#include <cstdint>

#define NF 40
#define NP 780        // 40*39/2
#define ED 64
#define AS 32
#define THREADS 256
#define CP 128        // pairs per chunk
#define NCH 7
#define NPAD (NCH*CP) // 896

#define PP 136        // IP tile pitch in f32 words (136 % 32 == 8 -> conflict-free frags)
#define WP 40         // W tile pitch  (40 % 32 == 8)

// ---- dynamic smem byte offsets ----
#define IPB_OFF   0        // IP big  [64][136] f32  34816
#define IPR_OFF   34816    // IP res  [64][136] f32  34816
#define WB_OFF    69632    // W big   [64][40]  f32  10240
#define WR_OFF    79872    // W res   [64][40]  f32  10240
#define XS_OFF    90112    // xs [40][65] f32        10400
#define OFFS_OFF  100512   // [896] u32               3584
#define LOG_OFF   104096   // [896] f32               3584
#define PART_OFF  107680   // [128][2] f32            1024
#define AB_OFF    108704   // 32 f32
#define PW_OFF    108832   // 32 f32
#define FW_OFF    108960   // 64 f32
#define RMAX_OFF  109216   // 8 f32
#define RSUM_OFF  109248   // 8 f32
#define RED_OFF   109280   // 64 f32
#define SMEM_TOTAL 109536  // x2 CTAs = 219072 <= 228KB/SM

__device__ __forceinline__ uint32_t tf32_of(float v) {
    uint32_t r; asm("cvt.rna.tf32.f32 %0, %1;" : "=r"(r) : "f"(v)); return r;
}

__device__ __forceinline__ void mma8(float& c0, float& c1, float& c2, float& c3,
                                     uint32_t a0, uint32_t a1, uint32_t a2, uint32_t a3,
                                     uint32_t b0, uint32_t b1) {
    asm("mma.sync.aligned.m16n8k8.row.col.f32.tf32.tf32.f32 "
        "{%0,%1,%2,%3}, {%4,%5,%6,%7}, {%8,%9}, {%0,%1,%2,%3};"
        : "+f"(c0), "+f"(c1), "+f"(c2), "+f"(c3)
        : "r"(a0), "r"(a1), "r"(a2), "r"(a3), "r"(b0), "r"(b1));
}

__global__ __launch_bounds__(THREADS, 2) void afm_kernel(
    const float* __restrict__ x,
    const float* __restrict__ attn_w,
    const float* __restrict__ attn_b,
    const float* __restrict__ proj_w,
    const float* __restrict__ proj_b,
    const float* __restrict__ fc_w,
    const float* __restrict__ fc_b,
    float* __restrict__ out)
{
    extern __shared__ char smem[];
    float* xs        = (float*)(smem + XS_OFF);
    float* logits_s  = (float*)(smem + LOG_OFF);
    float* part      = (float*)(smem + PART_OFF);
    float* ab_s      = (float*)(smem + AB_OFF);
    float* pw_s      = (float*)(smem + PW_OFF);
    float* fw_s      = (float*)(smem + FW_OFF);
    float* rmax      = (float*)(smem + RMAX_OFF);
    float* rsum      = (float*)(smem + RSUM_OFF);
    float* red_s     = (float*)(smem + RED_OFF);
    uint32_t* offs   = (uint32_t*)(smem + OFFS_OFF);
    uint32_t* IPBu   = (uint32_t*)(smem + IPB_OFF);
    uint32_t* IPRu   = (uint32_t*)(smem + IPR_OFF);
    uint32_t* WBu    = (uint32_t*)(smem + WB_OFF);
    uint32_t* WRu    = (uint32_t*)(smem + WR_OFF);

    const int tid  = threadIdx.x;
    const int lane = tid & 31;
    const int wid  = tid >> 5;
    const int b    = blockIdx.x;

    // ---- Phase 1: stage inputs ----
    const float* xb = x + (long long)b * (NF * ED);
    for (int idx = tid; idx < NF * ED; idx += THREADS)
        xs[(idx >> 6) * 65 + (idx & 63)] = xb[idx];

    // W big/res tf32 tiles [d][40]
    for (int e = tid; e < ED * AS; e += THREADS) {
        int d = e >> 5, n = e & 31;
        float w = attn_w[e];
        uint32_t big = tf32_of(w);
        uint32_t res = tf32_of(w - __uint_as_float(big));
        WBu[d * WP + n] = big;
        WRu[d * WP + n] = res;
    }

    if (tid < AS) { pw_s[tid] = proj_w[tid]; ab_s[tid] = attn_b[tid]; }
    if (tid < ED) fw_s[tid] = fc_w[tid];

    // packed xs byte-offsets per pair (dead pairs -> (0,0); harmless, never read out)
    for (int p = tid; p < NPAD; p += THREADS) {
        uint32_t o = 0;
        if (p < NP) {
            int i = 0, rem = p;
            while (rem >= NF - 1 - i) { rem -= NF - 1 - i; ++i; }
            int j = i + 1 + rem;
            o = (uint32_t)(i * 260) | ((uint32_t)(j * 260) << 16);
        }
        offs[p] = o;
    }
    const float pb = proj_b[0];
    __syncthreads();

    // ---- hoist B fragments (W) into registers: invariant across chunks ----
    const int kd   = lane & 3;        // threadID_in_group
    const int qr   = lane >> 2;       // groupID
    const int mgrp = wid & 3;         // 4 M-groups x 32 pairs
    const int ngrp = wid >> 2;        // 2 N-groups x 16 cols

    uint32_t Bb[8][2][2], Br[8][2][2];
#pragma unroll
    for (int kt = 0; kt < 8; ++kt) {
#pragma unroll
        for (int nt = 0; nt < 2; ++nt) {
            const int nc = ngrp * 16 + nt * 8 + qr;
            Bb[kt][nt][0] = WBu[(kt * 8 + kd) * WP + nc];
            Bb[kt][nt][1] = WBu[(kt * 8 + kd + 4) * WP + nc];
            Br[kt][nt][0] = WRu[(kt * 8 + kd) * WP + nc];
            Br[kt][nt][1] = WRu[(kt * 8 + kd + 4) * WP + nc];
        }
    }

    const uint4* offs4 = (const uint4*)(smem + OFFS_OFF);
    const char* xsc = (const char*)xs;
    const int pg = lane;

    // ---- Phase 2: chunked 3xtf32 MMA GEMM ----
    for (int t = 0; t < NCH; ++t) {
        const int cbase = t * CP;

        // build IP big/res tiles [d][pitch 136]
        {
            const uint4 oo = offs4[t * 32 + pg];
#pragma unroll
            for (int it = 0; it < 8; ++it) {
                const int d = wid + it * 8;
                const char* xsd = xsc + d * 4;
                float vx = *(const float*)(xsd + (oo.x & 0xffffu)) * *(const float*)(xsd + (oo.x >> 16));
                float vy = *(const float*)(xsd + (oo.y & 0xffffu)) * *(const float*)(xsd + (oo.y >> 16));
                float vz = *(const float*)(xsd + (oo.z & 0xffffu)) * *(const float*)(xsd + (oo.z >> 16));
                float vw = *(const float*)(xsd + (oo.w & 0xffffu)) * *(const float*)(xsd + (oo.w >> 16));
                uint4 big, res;
                big.x = tf32_of(vx); res.x = tf32_of(vx - __uint_as_float(big.x));
                big.y = tf32_of(vy); res.y = tf32_of(vy - __uint_as_float(big.y));
                big.z = tf32_of(vz); res.z = tf32_of(vz - __uint_as_float(big.z));
                big.w = tf32_of(vw); res.w = tf32_of(vw - __uint_as_float(big.w));
                *(uint4*)(IPBu + d * PP + pg * 4) = big;
                *(uint4*)(IPRu + d * PP + pg * 4) = res;
            }
        }
        __syncthreads();

        // accumulators init with bias
        float acc[2][2][4];
#pragma unroll
        for (int mt = 0; mt < 2; ++mt)
#pragma unroll
            for (int nt = 0; nt < 2; ++nt) {
                const int c0 = ngrp * 16 + nt * 8 + kd * 2;
                acc[mt][nt][0] = ab_s[c0];
                acc[mt][nt][1] = ab_s[c0 + 1];
                acc[mt][nt][2] = ab_s[c0];
                acc[mt][nt][3] = ab_s[c0 + 1];
            }

        // K loop: 8 kt x 2 mt x 2 nt x 3 mma
#pragma unroll
        for (int kt = 0; kt < 8; ++kt) {
#pragma unroll
            for (int mt = 0; mt < 2; ++mt) {
                const int pr = mgrp * 32 + mt * 16 + qr;
                const uint32_t* rb0 = IPBu + (kt * 8 + kd) * PP + pr;
                const uint32_t* rb1 = IPBu + (kt * 8 + kd + 4) * PP + pr;
                const uint32_t* rr0 = IPRu + (kt * 8 + kd) * PP + pr;
                const uint32_t* rr1 = IPRu + (kt * 8 + kd + 4) * PP + pr;
                uint32_t a0 = rb0[0], a1 = rb0[8], a2 = rb1[0], a3 = rb1[8];
                uint32_t r0 = rr0[0], r1 = rr0[8], r2 = rr1[0], r3 = rr1[8];
#pragma unroll
                for (int nt = 0; nt < 2; ++nt) {
                    mma8(acc[mt][nt][0], acc[mt][nt][1], acc[mt][nt][2], acc[mt][nt][3],
                         a0, a1, a2, a3, Bb[kt][nt][0], Bb[kt][nt][1]);
                    mma8(acc[mt][nt][0], acc[mt][nt][1], acc[mt][nt][2], acc[mt][nt][3],
                         a0, a1, a2, a3, Br[kt][nt][0], Br[kt][nt][1]);
                    mma8(acc[mt][nt][0], acc[mt][nt][1], acc[mt][nt][2], acc[mt][nt][3],
                         r0, r1, r2, r3, Bb[kt][nt][0], Bb[kt][nt][1]);
                }
            }
        }

        // epilogue: relu + proj, reduce over this warp's 16 cols, quad-reduce lanes
#pragma unroll
        for (int mt = 0; mt < 2; ++mt) {
            float lp0 = 0.f, lp1 = 0.f;
#pragma unroll
            for (int nt = 0; nt < 2; ++nt) {
                const int c0 = ngrp * 16 + nt * 8 + kd * 2;
                lp0 += fmaxf(acc[mt][nt][0], 0.f) * pw_s[c0] + fmaxf(acc[mt][nt][1], 0.f) * pw_s[c0 + 1];
                lp1 += fmaxf(acc[mt][nt][2], 0.f) * pw_s[c0] + fmaxf(acc[mt][nt][3], 0.f) * pw_s[c0 + 1];
            }
            lp0 += __shfl_xor_sync(0xffffffffu, lp0, 1);
            lp0 += __shfl_xor_sync(0xffffffffu, lp0, 2);
            lp1 += __shfl_xor_sync(0xffffffffu, lp1, 1);
            lp1 += __shfl_xor_sync(0xffffffffu, lp1, 2);
            if (kd == 0) {
                const int p0 = mgrp * 32 + mt * 16 + qr;
                part[p0 * 2 + ngrp]       = lp0;
                part[(p0 + 8) * 2 + ngrp] = lp1;
            }
        }
        __syncthreads();

        if (tid < CP) {
            const int p = cbase + tid;
            if (p < NP) logits_s[p] = part[tid * 2] + part[tid * 2 + 1] + pb;
        }
        // next chunk's build sync covers the logits write
    }
    __syncthreads();

    // ---- Phase 3: softmax over 780 (unnormalized; fold 1/S at end) ----
    float lm = -3.4e38f;
    for (int p = tid; p < NP; p += THREADS) lm = fmaxf(lm, logits_s[p]);
#pragma unroll
    for (int o = 16; o > 0; o >>= 1) lm = fmaxf(lm, __shfl_xor_sync(0xffffffffu, lm, o));
    if (lane == 0) rmax[wid] = lm;
    __syncthreads();

    float gmax = rmax[0];
#pragma unroll
    for (int wq = 1; wq < 8; ++wq) gmax = fmaxf(gmax, rmax[wq]);

    float ls = 0.f;
    for (int p = tid; p < NP; p += THREADS) {
        float e = __expf(logits_s[p] - gmax);
        logits_s[p] = e;
        ls += e;
    }
#pragma unroll
    for (int o = 16; o > 0; o >>= 1) ls += __shfl_xor_sync(0xffffffffu, ls, o);
    if (lane == 0) rsum[wid] = ls;
    __syncthreads();

    // ---- Phase 4: weighted sum over pairs (recompute ip), fc dot ----
    float* part4 = (float*)(smem + IPB_OFF);   // IP tiles dead; 8 warps x 64 dims
    float accL = 0.f, accH = 0.f;
    for (int p = wid; p < NP; p += 8) {
        const float s = logits_s[p];
        const uint32_t o = offs[p];
        const char* xi = xsc + (o & 0xffffu);
        const char* xj = xsc + (o >> 16);
        accL += s * (*(const float*)(xi + lane * 4)       * *(const float*)(xj + lane * 4));
        accH += s * (*(const float*)(xi + 128 + lane * 4) * *(const float*)(xj + 128 + lane * 4));
    }
    part4[wid * 64 + lane]      = accL;
    part4[wid * 64 + 32 + lane] = accH;
    __syncthreads();

    if (tid < 64) {
        float v = 0.f;
#pragma unroll
        for (int wq = 0; wq < 8; ++wq) v += part4[wq * 64 + tid];
        red_s[tid] = v * fw_s[tid];
    }
    __syncthreads();

    if (tid == 0) {
        float S = 0.f;
#pragma unroll
        for (int wq = 0; wq < 8; ++wq) S += rsum[wq];
        float tt = 0.f;
#pragma unroll
        for (int k = 0; k < 64; ++k) tt += red_s[k];
        out[b] = tt / S + fc_b[0];
    }
}

extern "C" void kernel_launch(void* const* d_in, const int* in_sizes, int n_in,
                              void* d_out, int out_size)
{
    const float* x      = (const float*)d_in[0];
    const float* attn_w = (const float*)d_in[1];
    const float* attn_b = (const float*)d_in[2];
    const float* proj_w = (const float*)d_in[3];
    const float* proj_b = (const float*)d_in[4];
    const float* fc_w   = (const float*)d_in[5];
    const float* fc_b   = (const float*)d_in[6];
    float* out = (float*)d_out;

    cudaFuncSetAttribute(afm_kernel, cudaFuncAttributeMaxDynamicSharedMemorySize, SMEM_TOTAL);
    afm_kernel<<<2048, THREADS, SMEM_TOTAL>>>(x, attn_w, attn_b, proj_w, proj_b, fc_w, fc_b, out);
}